// round 3
// baseline (speedup 1.0000x reference)
#include <cuda_runtime.h>
#include <cuda_fp16.h>
#include <cstdint>

#define NROWS 16384
#define NCODE 8192
#define DDIM  512

__device__ __half g_xh[(size_t)NROWS * DDIM];
__device__ __half g_eh[(size_t)NCODE * DDIM];

// ---------------- helpers ----------------
static __device__ __forceinline__ uint32_t smem_u32(const void* p) {
    uint32_t a;
    asm("{ .reg .u64 t; cvta.to.shared.u64 t, %1; cvt.u32.u64 %0, t; }" : "=r"(a) : "l"(p));
    return a;
}
static __device__ __forceinline__ void cp16(uint32_t dst, const void* src) {
    asm volatile("cp.async.cg.shared.global [%0], [%1], 16;"
                 :: "r"(dst), "l"(__cvta_generic_to_global(src)));
}
static __device__ __forceinline__ void ldsm_x4(uint32_t* r, uint32_t addr) {
    asm volatile("ldmatrix.sync.aligned.m8n8.x4.shared.b16 {%0,%1,%2,%3}, [%4];"
                 : "=r"(r[0]), "=r"(r[1]), "=r"(r[2]), "=r"(r[3]) : "r"(addr));
}
static __device__ __forceinline__ void mma16816(float* d, const uint32_t* a, const uint32_t* b) {
    asm volatile(
        "mma.sync.aligned.m16n8k16.row.col.f32.f16.f16.f32 "
        "{%0,%1,%2,%3},{%4,%5,%6,%7},{%8,%9},{%0,%1,%2,%3};"
        : "+f"(d[0]), "+f"(d[1]), "+f"(d[2]), "+f"(d[3])
        : "r"(a[0]), "r"(a[1]), "r"(a[2]), "r"(a[3]), "r"(b[0]), "r"(b[1]));
}

// ---------------- normalize rows -> f16 ----------------
__global__ __launch_bounds__(128) void k_norm(const float* __restrict__ in, int which) {
    __half* outh = which ? g_eh : g_xh;
    const int r = blockIdx.x, tid = threadIdx.x;
    const float4 v = ((const float4*)in)[(size_t)r * 128 + tid];
    float ss = v.x * v.x + v.y * v.y + v.z * v.z + v.w * v.w;
    #pragma unroll
    for (int o = 16; o; o >>= 1) ss += __shfl_down_sync(0xffffffffu, ss, o);
    __shared__ float sred[4];
    if ((tid & 31) == 0) sred[tid >> 5] = ss;
    __syncthreads();
    if (tid == 0) {
        float t = sred[0] + sred[1] + sred[2] + sred[3];
        sred[0] = 1.0f / fmaxf(sqrtf(t), 1e-12f);
    }
    __syncthreads();
    const float sc = sred[0];
    __half2* oh = (__half2*)outh;
    oh[(size_t)r * 256 + tid * 2]     = __floats2half2_rn(v.x * sc, v.y * sc);
    oh[(size_t)r * 256 + tid * 2 + 1] = __floats2half2_rn(v.z * sc, v.w * sc);
}

// ---------------- mma.sync GEMM: dist = Xn @ En^T ----------------
// CTA tile 128x128, K chunks of 64 (128B rows, SW128 xor swizzle), 3 stages.
// 8 warps (2 M x 4 N), warp tile 64x32.
#define TILE_BYTES (128 * 128)          /* one operand, one stage: 16 KB */
#define STG_BYTES  (2 * TILE_BYTES)     /* A + B: 32 KB */
#define GEMM_SMEM  (3 * STG_BYTES)      /* 96 KB */

static __device__ __forceinline__ void load_chunk(uint32_t abase, uint32_t bbase,
                                                  int m0, int n0, int k0, int tid) {
    #pragma unroll
    for (int i = 0; i < 4; i++) {
        int idx = tid + (i << 8);
        int row = idx >> 3, g = idx & 7;
        uint32_t dst = (uint32_t)(row * 128) + ((uint32_t)(g ^ (row & 7)) << 4);
        cp16(abase + dst, g_xh + (size_t)(m0 + row) * DDIM + k0 + g * 8);
        cp16(bbase + dst, g_eh + (size_t)(n0 + row) * DDIM + k0 + g * 8);
    }
    asm volatile("cp.async.commit_group;" ::: "memory");
}

__global__ __launch_bounds__(256, 1) void k_gemm(float* __restrict__ D) {
    extern __shared__ char smem[];
    const uint32_t sb = smem_u32(smem);
    const int tid = threadIdx.x, wid = tid >> 5, lane = tid & 31;
    const int n0 = blockIdx.x << 7, m0 = blockIdx.y << 7;
    const int wm = (wid >> 2) << 6;       // warp M offset: 0 or 64
    const int wn = (wid & 3) << 5;        // warp N offset: 0,32,64,96

    load_chunk(sb, sb + TILE_BYTES, m0, n0, 0, tid);
    load_chunk(sb + STG_BYTES, sb + STG_BYTES + TILE_BYTES, m0, n0, 64, tid);

    float acc[4][4][4];
    #pragma unroll
    for (int im = 0; im < 4; im++)
        #pragma unroll
        for (int jn = 0; jn < 4; jn++)
            #pragma unroll
            for (int q = 0; q < 4; q++) acc[im][jn][q] = 0.f;

    // precomputed per-lane ldmatrix row/col pieces
    const int a_row = wm + (lane & 15);          // + im*16
    const int a_hi  = lane >> 4;                 // chunk bit
    const int b_row = wn + (lane & 7) + (((lane >> 4) & 1) << 3);  // + ng*16
    const int b_hi  = (lane >> 3) & 1;

    #pragma unroll 1
    for (int i = 0; i < 8; i++) {
        if (i == 6) asm volatile("cp.async.wait_group 0;" ::: "memory");
        else        asm volatile("cp.async.wait_group 1;" ::: "memory");
        __syncthreads();
        if (i + 2 < 8)
            load_chunk(sb + ((i + 2) % 3) * STG_BYTES,
                       sb + ((i + 2) % 3) * STG_BYTES + TILE_BYTES, m0, n0, (i + 2) * 64, tid);
        const uint32_t abase = sb + (i % 3) * STG_BYTES;
        const uint32_t bbase = abase + TILE_BYTES;
        #pragma unroll
        for (int ks = 0; ks < 4; ks++) {
            uint32_t af[4][4], bf[4][2];
            #pragma unroll
            for (int im = 0; im < 4; im++) {
                int row = a_row + im * 16;
                uint32_t col = (uint32_t)((ks * 2 + a_hi) ^ (row & 7)) << 4;
                ldsm_x4(af[im], abase + row * 128 + col);
            }
            #pragma unroll
            for (int ng = 0; ng < 2; ng++) {
                int row = b_row + ng * 16;
                uint32_t col = (uint32_t)((ks * 2 + b_hi) ^ (row & 7)) << 4;
                uint32_t t[4];
                ldsm_x4(t, bbase + row * 128 + col);
                bf[2 * ng][0] = t[0]; bf[2 * ng][1] = t[1];
                bf[2 * ng + 1][0] = t[2]; bf[2 * ng + 1][1] = t[3];
            }
            #pragma unroll
            for (int im = 0; im < 4; im++)
                #pragma unroll
                for (int jn = 0; jn < 4; jn++)
                    mma16816(acc[im][jn], af[im], bf[jn]);
        }
    }

    // epilogue: direct stores (float2), sectors fully covered within quad groups
    const int g = lane >> 2, tig = lane & 3;
    float* dbase = D + (size_t)(m0 + wm + g) * NCODE + n0 + wn + tig * 2;
    #pragma unroll
    for (int im = 0; im < 4; im++) {
        #pragma unroll
        for (int jn = 0; jn < 4; jn++) {
            float* p = dbase + (size_t)(im * 16) * NCODE + jn * 8;
            *(float2*)p                      = make_float2(acc[im][jn][0], acc[im][jn][1]);
            *(float2*)(p + (size_t)8 * NCODE) = make_float2(acc[im][jn][2], acc[im][jn][3]);
        }
    }
}

// ---------------- argmax + exact refine + gather ----------------
#define MAXC 128
__global__ __launch_bounds__(256) void k_refine(
    const float* __restrict__ dist, const float* __restrict__ x,
    const float* __restrict__ e, float* __restrict__ qout, float* __restrict__ iout) {
    const int r = blockIdx.x, tid = threadIdx.x;
    const int lane = tid & 31, wid = tid >> 5;
    const float4* drow = (const float4*)(dist + (size_t)r * NCODE);

    float4 v4[8];
    float bv = -1e30f;
    #pragma unroll
    for (int j = 0; j < 8; j++) {
        float4 v = drow[tid + j * 256];
        v4[j] = v;
        bv = fmaxf(bv, fmaxf(fmaxf(v.x, v.y), fmaxf(v.z, v.w)));
    }
    __shared__ float sv[256];
    sv[tid] = bv;
    __syncthreads();
    for (int s = 128; s > 0; s >>= 1) {
        if (tid < s) sv[tid] = fmaxf(sv[tid], sv[tid + s]);
        __syncthreads();
    }
    const float thr = sv[0] - 0.005f;

    __shared__ int clist[MAXC];
    __shared__ int ccnt;
    if (tid == 0) ccnt = 0;
    __syncthreads();
    #pragma unroll
    for (int j = 0; j < 8; j++) {
        float4 v = v4[j];
        int c0 = (tid + j * 256) * 4;
        if (v.x >= thr) { int p = atomicAdd(&ccnt, 1); if (p < MAXC) clist[p] = c0; }
        if (v.y >= thr) { int p = atomicAdd(&ccnt, 1); if (p < MAXC) clist[p] = c0 + 1; }
        if (v.z >= thr) { int p = atomicAdd(&ccnt, 1); if (p < MAXC) clist[p] = c0 + 2; }
        if (v.w >= thr) { int p = atomicAdd(&ccnt, 1); if (p < MAXC) clist[p] = c0 + 3; }
    }
    __syncthreads();
    const int nc = min(ccnt, MAXC);

    __shared__ double cval[MAXC];
    __shared__ float cinv[MAXC];
    const float* xr = x + (size_t)r * DDIM;
    for (int cI = wid; cI < nc; cI += 8) {
        const float* er = e + (size_t)clist[cI] * DDIM;
        float s = 0.f, comp = 0.f, es = 0.f, ecomp = 0.f;
        for (int k = lane; k < DDIM; k += 32) {
            float a = xr[k], b = er[k];
            float p = __fmul_rn(a, b);
            float pe = __fmaf_rn(a, b, -p);
            float t = __fadd_rn(s, p);
            float z = __fsub_rn(t, s);
            comp = __fadd_rn(comp, __fadd_rn(__fsub_rn(s, __fsub_rn(t, z)), __fsub_rn(p, z)));
            s = t; comp = __fadd_rn(comp, pe);
            float q2 = __fmul_rn(b, b);
            float qe = __fmaf_rn(b, b, -q2);
            float t2 = __fadd_rn(es, q2);
            float z2 = __fsub_rn(t2, es);
            ecomp = __fadd_rn(ecomp, __fadd_rn(__fsub_rn(es, __fsub_rn(t2, z2)), __fsub_rn(q2, z2)));
            es = t2; ecomp = __fadd_rn(ecomp, qe);
        }
        double ds = (double)s + (double)comp;
        double de = (double)es + (double)ecomp;
        #pragma unroll
        for (int o = 16; o; o >>= 1) {
            ds += __shfl_down_sync(0xffffffffu, ds, o);
            de += __shfl_down_sync(0xffffffffu, de, o);
        }
        if (lane == 0) {
            double ne = sqrt(de);
            cval[cI] = ds / ne;
            cinv[cI] = (float)(1.0 / (ne > 1e-12 ? ne : 1e-12));
        }
    }
    __syncthreads();
    __shared__ int wcol_s;
    __shared__ float winv_s;
    if (tid == 0) {
        double best = -1e300; int bc = 0x7fffffff; float bi = 0.f;
        for (int c = 0; c < nc; c++) {
            double v = cval[c]; int col = clist[c];
            if (v > best || (v == best && col < bc)) { best = v; bc = col; bi = cinv[c]; }
        }
        wcol_s = bc; winv_s = bi;
        iout[r] = (float)bc;
    }
    __syncthreads();
    const float* ew = e + (size_t)wcol_s * DDIM;
    const float wi = winv_s;
    qout[(size_t)r * DDIM + tid]       = ew[tid] * wi;
    qout[(size_t)r * DDIM + tid + 256] = ew[tid + 256] * wi;
}

// ---------------- launch ----------------
extern "C" void kernel_launch(void* const* d_in, const int* in_sizes, int n_in,
                              void* d_out, int out_size) {
    (void)in_sizes; (void)n_in; (void)out_size;
    const float* x = (const float*)d_in[0];
    const float* e = (const float*)d_in[1];
    float* qout = (float*)d_out;
    float* iout = qout + (size_t)NROWS * DDIM;
    float* dist = iout + NROWS;

    cudaFuncSetAttribute(k_gemm, cudaFuncAttributeMaxDynamicSharedMemorySize, GEMM_SMEM);
    k_norm<<<NROWS, 128>>>(x, 0);
    k_norm<<<NCODE, 128>>>(e, 1);
    dim3 gg(NCODE / 128, NROWS / 128);
    k_gemm<<<gg, 256, GEMM_SMEM>>>(dist);
    k_refine<<<NROWS, 256>>>(dist, x, e, qout, iout);
}

// round 4
// speedup vs baseline: 1.0664x; 1.0664x over previous
#include <cuda_runtime.h>
#include <cuda_fp16.h>
#include <cstdint>

#define NROWS 16384
#define NCODE 8192
#define DDIM  512
#define NTILE 256
#define NTILES (NCODE / NTILE)   /* 32 */

__device__ __half g_xh[(size_t)NROWS * DDIM];
__device__ __half g_eh[(size_t)NCODE * DDIM];
__device__ float  g_tmax[(size_t)NROWS * NTILES];

// ---------------- helpers ----------------
static __device__ __forceinline__ uint32_t smem_u32(const void* p) {
    uint32_t a;
    asm("{ .reg .u64 t; cvta.to.shared.u64 t, %1; cvt.u32.u64 %0, t; }" : "=r"(a) : "l"(p));
    return a;
}
static __device__ __forceinline__ void cp16(uint32_t dst, const void* src) {
    asm volatile("cp.async.cg.shared.global [%0], [%1], 16;"
                 :: "r"(dst), "l"(__cvta_generic_to_global(src)));
}
static __device__ __forceinline__ void ldsm_x4(uint32_t* r, uint32_t addr) {
    asm volatile("ldmatrix.sync.aligned.m8n8.x4.shared.b16 {%0,%1,%2,%3}, [%4];"
                 : "=r"(r[0]), "=r"(r[1]), "=r"(r[2]), "=r"(r[3]) : "r"(addr));
}
static __device__ __forceinline__ void mma16816(float* d, const uint32_t* a, const uint32_t* b) {
    asm volatile(
        "mma.sync.aligned.m16n8k16.row.col.f32.f16.f16.f32 "
        "{%0,%1,%2,%3},{%4,%5,%6,%7},{%8,%9},{%0,%1,%2,%3};"
        : "+f"(d[0]), "+f"(d[1]), "+f"(d[2]), "+f"(d[3])
        : "r"(a[0]), "r"(a[1]), "r"(a[2]), "r"(a[3]), "r"(b[0]), "r"(b[1]));
}

// ---------------- normalize rows -> f16 (x and e in one launch) ------------
__global__ __launch_bounds__(128) void k_norm(const float* __restrict__ x,
                                              const float* __restrict__ e) {
    const int b = blockIdx.x, tid = threadIdx.x;
    const float* in;
    __half* out;
    if (b < NROWS) { in = x + (size_t)b * DDIM; out = g_xh + (size_t)b * DDIM; }
    else { in = e + (size_t)(b - NROWS) * DDIM; out = g_eh + (size_t)(b - NROWS) * DDIM; }
    const float4 v = ((const float4*)in)[tid];
    float ss = v.x * v.x + v.y * v.y + v.z * v.z + v.w * v.w;
    #pragma unroll
    for (int o = 16; o; o >>= 1) ss += __shfl_down_sync(0xffffffffu, ss, o);
    __shared__ float sred[4];
    if ((tid & 31) == 0) sred[tid >> 5] = ss;
    __syncthreads();
    if (tid == 0) {
        float t = sred[0] + sred[1] + sred[2] + sred[3];
        sred[0] = 1.0f / fmaxf(sqrtf(t), 1e-12f);
    }
    __syncthreads();
    const float sc = sred[0];
    __half2* oh = (__half2*)out;
    oh[tid * 2]     = __floats2half2_rn(v.x * sc, v.y * sc);
    oh[tid * 2 + 1] = __floats2half2_rn(v.z * sc, v.w * sc);
}

// ---------------- mma.sync GEMM: dist = Xn @ En^T, CTA 128x256 --------------
#define A_BYTES (128 * 128)             /* 16 KB */
#define B_BYTES (256 * 128)             /* 32 KB */
#define STG_BYTES (A_BYTES + B_BYTES)   /* 48 KB */
#define GEMM_SMEM (3 * STG_BYTES)       /* 144 KB */

static __device__ __forceinline__ void load_chunk(uint32_t abase, uint32_t bbase,
                                                  int m0, int n0, int k0, int tid) {
    #pragma unroll
    for (int i = 0; i < 4; i++) {   // A: 128 rows x 8 groups
        int idx = tid + (i << 8);
        int row = idx >> 3, g = idx & 7;
        uint32_t dst = (uint32_t)(row * 128) + ((uint32_t)(g ^ (row & 7)) << 4);
        cp16(abase + dst, g_xh + (size_t)(m0 + row) * DDIM + k0 + g * 8);
    }
    #pragma unroll
    for (int i = 0; i < 8; i++) {   // B: 256 rows x 8 groups
        int idx = tid + (i << 8);
        int row = idx >> 3, g = idx & 7;
        uint32_t dst = (uint32_t)(row * 128) + ((uint32_t)(g ^ (row & 7)) << 4);
        cp16(bbase + dst, g_eh + (size_t)(n0 + row) * DDIM + k0 + g * 8);
    }
    asm volatile("cp.async.commit_group;" ::: "memory");
}

__global__ __launch_bounds__(256, 1) void k_gemm(float* __restrict__ D) {
    extern __shared__ char smem[];
    const uint32_t sb = smem_u32(smem);
    const int tid = threadIdx.x, wid = tid >> 5, lane = tid & 31;
    const int n0 = blockIdx.x << 8, m0 = blockIdx.y << 7;
    const int wm = (wid >> 2) << 6;       // 0 or 64
    const int wn = (wid & 3) << 6;        // 0,64,128,192

    load_chunk(sb, sb + A_BYTES, m0, n0, 0, tid);
    load_chunk(sb + STG_BYTES, sb + STG_BYTES + A_BYTES, m0, n0, 64, tid);

    float acc[4][8][4];
    #pragma unroll
    for (int im = 0; im < 4; im++)
        #pragma unroll
        for (int jn = 0; jn < 8; jn++)
            #pragma unroll
            for (int q = 0; q < 4; q++) acc[im][jn][q] = 0.f;

    const int a_row = wm + (lane & 15);
    const int a_hi  = lane >> 4;
    const int b_row = wn + (lane & 7) + (((lane >> 4) & 1) << 3);
    const int b_hi  = (lane >> 3) & 1;

    #pragma unroll 1
    for (int i = 0; i < 8; i++) {
        if (i == 7) asm volatile("cp.async.wait_group 0;" ::: "memory");
        else        asm volatile("cp.async.wait_group 1;" ::: "memory");
        __syncthreads();
        if (i + 2 < 8)
            load_chunk(sb + ((i + 2) % 3) * STG_BYTES,
                       sb + ((i + 2) % 3) * STG_BYTES + A_BYTES, m0, n0, (i + 2) * 64, tid);
        const uint32_t abase = sb + (i % 3) * STG_BYTES;
        const uint32_t bbase = abase + A_BYTES;
        #pragma unroll
        for (int ks = 0; ks < 4; ks++) {
            uint32_t af[4][4], bf[8][2];
            #pragma unroll
            for (int im = 0; im < 4; im++) {
                int row = a_row + im * 16;
                uint32_t col = (uint32_t)((ks * 2 + a_hi) ^ (row & 7)) << 4;
                ldsm_x4(af[im], abase + row * 128 + col);
            }
            #pragma unroll
            for (int ng = 0; ng < 4; ng++) {
                int row = b_row + ng * 16;
                uint32_t col = (uint32_t)((ks * 2 + b_hi) ^ (row & 7)) << 4;
                uint32_t t[4];
                ldsm_x4(t, bbase + row * 128 + col);
                bf[2 * ng][0] = t[0]; bf[2 * ng][1] = t[1];
                bf[2 * ng + 1][0] = t[2]; bf[2 * ng + 1][1] = t[3];
            }
            #pragma unroll
            for (int im = 0; im < 4; im++)
                #pragma unroll
                for (int jn = 0; jn < 8; jn++)
                    mma16816(acc[im][jn], af[im], bf[jn]);
        }
    }

    // ---- dist stores (direct, coalesced within quads) ----
    const int g = lane >> 2, tig = lane & 3;
    float* dbase = D + (size_t)(m0 + wm + g) * NCODE + n0 + wn + tig * 2;
    #pragma unroll
    for (int im = 0; im < 4; im++) {
        #pragma unroll
        for (int jn = 0; jn < 8; jn++) {
            float* p = dbase + (size_t)(im * 16) * NCODE + jn * 8;
            *(float2*)p                       = make_float2(acc[im][jn][0], acc[im][jn][1]);
            *(float2*)(p + (size_t)8 * NCODE) = make_float2(acc[im][jn][2], acc[im][jn][3]);
        }
    }

    // ---- per-row tile max -> g_tmax[row][blockIdx.x] ----
    float rmax[4][2];
    #pragma unroll
    for (int im = 0; im < 4; im++) {
        float m0v = -1e30f, m1v = -1e30f;
        #pragma unroll
        for (int jn = 0; jn < 8; jn++) {
            m0v = fmaxf(m0v, fmaxf(acc[im][jn][0], acc[im][jn][1]));
            m1v = fmaxf(m1v, fmaxf(acc[im][jn][2], acc[im][jn][3]));
        }
        rmax[im][0] = m0v; rmax[im][1] = m1v;
    }
    #pragma unroll
    for (int im = 0; im < 4; im++)
        #pragma unroll
        for (int h = 0; h < 2; h++) {
            float v = rmax[im][h];
            v = fmaxf(v, __shfl_xor_sync(0xffffffffu, v, 1));
            v = fmaxf(v, __shfl_xor_sync(0xffffffffu, v, 2));
            rmax[im][h] = v;
        }
    __syncthreads();                       // stage smem no longer needed
    float* smax = (float*)smem;            // [128][4]
    if (tig == 0) {
        #pragma unroll
        for (int im = 0; im < 4; im++)
            #pragma unroll
            for (int h = 0; h < 2; h++)
                smax[(wm + im * 16 + h * 8 + g) * 4 + (wid & 3)] = rmax[im][h];
    }
    __syncthreads();
    if (tid < 128) {
        float m = fmaxf(fmaxf(smax[tid * 4], smax[tid * 4 + 1]),
                        fmaxf(smax[tid * 4 + 2], smax[tid * 4 + 3]));
        g_tmax[(size_t)(m0 + tid) * NTILES + blockIdx.x] = m;
    }
}

// ---------------- refine: tile-pruned candidate scan + exact rescore --------
#define MAXC 128
__global__ __launch_bounds__(256) void k_refine(
    const float* __restrict__ dist, const float* __restrict__ x,
    const float* __restrict__ e, float* __restrict__ qout, float* __restrict__ iout) {
    const int r = blockIdx.x, tid = threadIdx.x;
    const int lane = tid & 31, wid = tid >> 5;

    __shared__ float thr_s;
    __shared__ int clist[MAXC];
    __shared__ int ccnt;
    if (tid < 32) {
        float v = g_tmax[(size_t)r * NTILES + tid];
        #pragma unroll
        for (int o = 16; o; o >>= 1) v = fmaxf(v, __shfl_xor_sync(0xffffffffu, v, o));
        if (tid == 0) { thr_s = v - 0.005f; ccnt = 0; }
    }
    __syncthreads();
    const float thr = thr_s;

    const float* drow = dist + (size_t)r * NCODE;
    for (int t = 0; t < NTILES; t++) {
        if (g_tmax[(size_t)r * NTILES + t] >= thr) {
            float v = drow[t * NTILE + tid];
            if (v >= thr) {
                int p = atomicAdd(&ccnt, 1);
                if (p < MAXC) clist[p] = t * NTILE + tid;
            }
        }
    }
    __syncthreads();
    const int nc = min(ccnt, MAXC);

    __shared__ double cval[MAXC];
    __shared__ float cinv[MAXC];
    const float* xr = x + (size_t)r * DDIM;
    for (int cI = wid; cI < nc; cI += 8) {
        const float* er = e + (size_t)clist[cI] * DDIM;
        float s = 0.f, comp = 0.f, es = 0.f, ecomp = 0.f;
        for (int k = lane; k < DDIM; k += 32) {
            float a = xr[k], b = er[k];
            float p = __fmul_rn(a, b);
            float pe = __fmaf_rn(a, b, -p);
            float t = __fadd_rn(s, p);
            float z = __fsub_rn(t, s);
            comp = __fadd_rn(comp, __fadd_rn(__fsub_rn(s, __fsub_rn(t, z)), __fsub_rn(p, z)));
            s = t; comp = __fadd_rn(comp, pe);
            float q2 = __fmul_rn(b, b);
            float qe = __fmaf_rn(b, b, -q2);
            float t2 = __fadd_rn(es, q2);
            float z2 = __fsub_rn(t2, es);
            ecomp = __fadd_rn(ecomp, __fadd_rn(__fsub_rn(es, __fsub_rn(t2, z2)), __fsub_rn(q2, z2)));
            es = t2; ecomp = __fadd_rn(ecomp, qe);
        }
        double ds = (double)s + (double)comp;
        double de = (double)es + (double)ecomp;
        #pragma unroll
        for (int o = 16; o; o >>= 1) {
            ds += __shfl_down_sync(0xffffffffu, ds, o);
            de += __shfl_down_sync(0xffffffffu, de, o);
        }
        if (lane == 0) {
            double ne = sqrt(de);
            cval[cI] = ds / ne;
            cinv[cI] = (float)(1.0 / (ne > 1e-12 ? ne : 1e-12));
        }
    }
    __syncthreads();
    __shared__ int wcol_s;
    __shared__ float winv_s;
    if (tid == 0) {
        double best = -1e300; int bc = 0x7fffffff; float bi = 0.f;
        for (int c = 0; c < nc; c++) {
            double v = cval[c]; int col = clist[c];
            if (v > best || (v == best && col < bc)) { best = v; bc = col; bi = cinv[c]; }
        }
        wcol_s = bc; winv_s = bi;
        iout[r] = (float)bc;
    }
    __syncthreads();
    const float* ew = e + (size_t)wcol_s * DDIM;
    const float wi = winv_s;
    qout[(size_t)r * DDIM + tid]       = ew[tid] * wi;
    qout[(size_t)r * DDIM + tid + 256] = ew[tid + 256] * wi;
}

// ---------------- launch ----------------
extern "C" void kernel_launch(void* const* d_in, const int* in_sizes, int n_in,
                              void* d_out, int out_size) {
    (void)in_sizes; (void)n_in; (void)out_size;
    const float* x = (const float*)d_in[0];
    const float* e = (const float*)d_in[1];
    float* qout = (float*)d_out;
    float* iout = qout + (size_t)NROWS * DDIM;
    float* dist = iout + NROWS;

    cudaFuncSetAttribute(k_gemm, cudaFuncAttributeMaxDynamicSharedMemorySize, GEMM_SMEM);
    k_norm<<<NROWS + NCODE, 128>>>(x, e);
    dim3 gg(NCODE / NTILE, NROWS / 128);
    k_gemm<<<gg, 256, GEMM_SMEM>>>(dist);
    k_refine<<<NROWS, 256>>>(dist, x, e, qout, iout);
}

// round 5
// speedup vs baseline: 1.1235x; 1.0535x over previous
#include <cuda_runtime.h>
#include <cuda_fp16.h>
#include <cstdint>

#define NROWS 16384
#define NCODE 8192
#define DDIM  512
#define NTILE 128
#define NTILES (NCODE / NTILE)   /* 64 */

__device__ __half g_xh[(size_t)NROWS * DDIM];
__device__ __half g_eh[(size_t)NCODE * DDIM];
__device__ float  g_tmax[(size_t)NROWS * NTILES];

// ---------------- helpers ----------------
static __device__ __forceinline__ uint32_t smem_u32(const void* p) {
    uint32_t a;
    asm("{ .reg .u64 t; cvta.to.shared.u64 t, %1; cvt.u32.u64 %0, t; }" : "=r"(a) : "l"(p));
    return a;
}
static __device__ __forceinline__ void cp16(uint32_t dst, const void* src) {
    asm volatile("cp.async.cg.shared.global [%0], [%1], 16;"
                 :: "r"(dst), "l"(__cvta_generic_to_global(src)));
}
static __device__ __forceinline__ void ldsm_x4(uint32_t* r, uint32_t addr) {
    asm volatile("ldmatrix.sync.aligned.m8n8.x4.shared.b16 {%0,%1,%2,%3}, [%4];"
                 : "=r"(r[0]), "=r"(r[1]), "=r"(r[2]), "=r"(r[3]) : "r"(addr));
}
static __device__ __forceinline__ void mma16816(float* d, const uint32_t* a, const uint32_t* b) {
    asm volatile(
        "mma.sync.aligned.m16n8k16.row.col.f32.f16.f16.f32 "
        "{%0,%1,%2,%3},{%4,%5,%6,%7},{%8,%9},{%0,%1,%2,%3};"
        : "+f"(d[0]), "+f"(d[1]), "+f"(d[2]), "+f"(d[3])
        : "r"(a[0]), "r"(a[1]), "r"(a[2]), "r"(a[3]), "r"(b[0]), "r"(b[1]));
}

// ---------------- normalize rows -> f16 ----------------
__global__ __launch_bounds__(128) void k_norm(const float* __restrict__ x,
                                              const float* __restrict__ e) {
    const int b = blockIdx.x, tid = threadIdx.x;
    const float* in;
    __half* out;
    if (b < NROWS) { in = x + (size_t)b * DDIM; out = g_xh + (size_t)b * DDIM; }
    else { in = e + (size_t)(b - NROWS) * DDIM; out = g_eh + (size_t)(b - NROWS) * DDIM; }
    const float4 v = ((const float4*)in)[tid];
    float ss = v.x * v.x + v.y * v.y + v.z * v.z + v.w * v.w;
    #pragma unroll
    for (int o = 16; o; o >>= 1) ss += __shfl_down_sync(0xffffffffu, ss, o);
    __shared__ float sred[4];
    if ((tid & 31) == 0) sred[tid >> 5] = ss;
    __syncthreads();
    if (tid == 0) {
        float t = sred[0] + sred[1] + sred[2] + sred[3];
        sred[0] = 1.0f / fmaxf(sqrtf(t), 1e-12f);
    }
    __syncthreads();
    const float sc = sred[0];
    __half2* oh = (__half2*)out;
    oh[tid * 2]     = __floats2half2_rn(v.x * sc, v.y * sc);
    oh[tid * 2 + 1] = __floats2half2_rn(v.z * sc, v.w * sc);
}

// ---------------- mma.sync GEMM: dist = Xn @ En^T ----------------
// CTA 128x128, 128 threads (2x2 warps), warp tile 64x64, 3 stages, reg dbuf.
#define T_BYTES (128 * 128)             /* 16 KB per operand per stage */
#define STG_BYTES (2 * T_BYTES)         /* 32 KB */
#define GEMM_SMEM (3 * STG_BYTES)       /* 96 KB */

static __device__ __forceinline__ void load_chunk(uint32_t abase, uint32_t bbase,
                                                  int m0, int n0, int k0, int tid) {
    #pragma unroll
    for (int i = 0; i < 8; i++) {
        int idx = tid + (i << 7);
        int row = idx >> 3, g = idx & 7;
        uint32_t dst = (uint32_t)(row * 128) + ((uint32_t)(g ^ (row & 7)) << 4);
        cp16(abase + dst, g_xh + (size_t)(m0 + row) * DDIM + k0 + g * 8);
        cp16(bbase + dst, g_eh + (size_t)(n0 + row) * DDIM + k0 + g * 8);
    }
    asm volatile("cp.async.commit_group;" ::: "memory");
}

static __device__ __forceinline__ void load_frags(
    uint32_t abase, uint32_t bbase, int ks,
    uint32_t af[4][4], uint32_t bf[8][2],
    int a_row, int a_hi, int b_row, int b_hi) {
    #pragma unroll
    for (int im = 0; im < 4; im++) {
        int row = a_row + im * 16;
        uint32_t col = (uint32_t)((ks * 2 + a_hi) ^ (row & 7)) << 4;
        ldsm_x4(af[im], abase + row * 128 + col);
    }
    #pragma unroll
    for (int ng = 0; ng < 4; ng++) {
        int row = b_row + ng * 16;
        uint32_t col = (uint32_t)((ks * 2 + b_hi) ^ (row & 7)) << 4;
        uint32_t t[4];
        ldsm_x4(t, bbase + row * 128 + col);
        bf[2 * ng][0] = t[0]; bf[2 * ng][1] = t[1];
        bf[2 * ng + 1][0] = t[2]; bf[2 * ng + 1][1] = t[3];
    }
}

__global__ __launch_bounds__(128, 2) void k_gemm(float* __restrict__ D) {
    extern __shared__ char smem[];
    const uint32_t sb = smem_u32(smem);
    const int tid = threadIdx.x, wid = tid >> 5, lane = tid & 31;
    const int n0 = blockIdx.x << 7, m0 = blockIdx.y << 7;
    const int wm = (wid >> 1) << 6;       // 0 or 64
    const int wn = (wid & 1) << 6;        // 0 or 64

    load_chunk(sb, sb + T_BYTES, m0, n0, 0, tid);
    load_chunk(sb + STG_BYTES, sb + STG_BYTES + T_BYTES, m0, n0, 64, tid);

    float acc[4][8][4];
    #pragma unroll
    for (int im = 0; im < 4; im++)
        #pragma unroll
        for (int jn = 0; jn < 8; jn++)
            #pragma unroll
            for (int q = 0; q < 4; q++) acc[im][jn][q] = 0.f;

    const int a_row = wm + (lane & 15);
    const int a_hi  = lane >> 4;
    const int b_row = wn + (lane & 7) + (((lane >> 4) & 1) << 3);
    const int b_hi  = (lane >> 3) & 1;

    uint32_t af[2][4][4], bf[2][8][2];

    #pragma unroll 1
    for (int i = 0; i < 8; i++) {
        if (i == 7) asm volatile("cp.async.wait_group 0;" ::: "memory");
        else        asm volatile("cp.async.wait_group 1;" ::: "memory");
        __syncthreads();
        if (i + 2 < 8)
            load_chunk(sb + ((i + 2) % 3) * STG_BYTES,
                       sb + ((i + 2) % 3) * STG_BYTES + T_BYTES, m0, n0, (i + 2) * 64, tid);
        const uint32_t abase = sb + (i % 3) * STG_BYTES;
        const uint32_t bbase = abase + T_BYTES;
        load_frags(abase, bbase, 0, af[0], bf[0], a_row, a_hi, b_row, b_hi);
        #pragma unroll
        for (int ks = 0; ks < 4; ks++) {
            if (ks < 3)
                load_frags(abase, bbase, ks + 1, af[(ks + 1) & 1], bf[(ks + 1) & 1],
                           a_row, a_hi, b_row, b_hi);
            #pragma unroll
            for (int im = 0; im < 4; im++)
                #pragma unroll
                for (int jn = 0; jn < 8; jn++)
                    mma16816(acc[im][jn], af[ks & 1][im], bf[ks & 1][jn]);
        }
    }

    // ---- dist stores ----
    const int g = lane >> 2, tig = lane & 3;
    float* dbase = D + (size_t)(m0 + wm + g) * NCODE + n0 + wn + tig * 2;
    #pragma unroll
    for (int im = 0; im < 4; im++) {
        #pragma unroll
        for (int jn = 0; jn < 8; jn++) {
            float* p = dbase + (size_t)(im * 16) * NCODE + jn * 8;
            *(float2*)p                       = make_float2(acc[im][jn][0], acc[im][jn][1]);
            *(float2*)(p + (size_t)8 * NCODE) = make_float2(acc[im][jn][2], acc[im][jn][3]);
        }
    }

    // ---- per-row tile max -> g_tmax[row][blockIdx.x] ----
    float rmax[4][2];
    #pragma unroll
    for (int im = 0; im < 4; im++) {
        float m0v = -1e30f, m1v = -1e30f;
        #pragma unroll
        for (int jn = 0; jn < 8; jn++) {
            m0v = fmaxf(m0v, fmaxf(acc[im][jn][0], acc[im][jn][1]));
            m1v = fmaxf(m1v, fmaxf(acc[im][jn][2], acc[im][jn][3]));
        }
        rmax[im][0] = m0v; rmax[im][1] = m1v;
    }
    #pragma unroll
    for (int im = 0; im < 4; im++)
        #pragma unroll
        for (int h = 0; h < 2; h++) {
            float v = rmax[im][h];
            v = fmaxf(v, __shfl_xor_sync(0xffffffffu, v, 1));
            v = fmaxf(v, __shfl_xor_sync(0xffffffffu, v, 2));
            rmax[im][h] = v;
        }
    __syncthreads();
    float* smax = (float*)smem;            // [128][2]
    if (tig == 0) {
        #pragma unroll
        for (int im = 0; im < 4; im++)
            #pragma unroll
            for (int h = 0; h < 2; h++)
                smax[(wm + im * 16 + h * 8 + g) * 2 + (wid & 1)] = rmax[im][h];
    }
    __syncthreads();
    float m = fmaxf(smax[tid * 2], smax[tid * 2 + 1]);
    g_tmax[(size_t)(m0 + tid) * NTILES + blockIdx.x] = m;
}

// ---------------- refine ----------------
#define MAXC 128
__global__ __launch_bounds__(256) void k_refine(
    const float* __restrict__ dist, const float* __restrict__ x,
    const float* __restrict__ e, float* __restrict__ qout, float* __restrict__ iout) {
    const int r = blockIdx.x, tid = threadIdx.x;
    const int lane = tid & 31, wid = tid >> 5;

    __shared__ float tmaxs[NTILES];
    __shared__ float thr_s;
    __shared__ int clist[MAXC];
    __shared__ int ccnt;
    if (tid < NTILES) tmaxs[tid] = g_tmax[(size_t)r * NTILES + tid];
    __syncthreads();
    if (tid < 32) {
        float v = fmaxf(tmaxs[tid], tmaxs[tid + 32]);
        #pragma unroll
        for (int o = 16; o; o >>= 1) v = fmaxf(v, __shfl_xor_sync(0xffffffffu, v, o));
        if (tid == 0) { thr_s = v - 0.005f; ccnt = 0; }
    }
    __syncthreads();
    const float thr = thr_s;

    const float* drow = dist + (size_t)r * NCODE;
    for (int t = 0; t < NTILES; t++) {
        if (tmaxs[t] >= thr && tid < NTILE) {
            float v = drow[t * NTILE + tid];
            if (v >= thr) {
                int p = atomicAdd(&ccnt, 1);
                if (p < MAXC) clist[p] = t * NTILE + tid;
            }
        }
    }
    __syncthreads();
    const int nc = min(ccnt, MAXC);

    __shared__ double cval[MAXC];
    __shared__ float cinv[MAXC];
    const float* xr = x + (size_t)r * DDIM;
    for (int cI = wid; cI < nc; cI += 8) {
        const float* er = e + (size_t)clist[cI] * DDIM;
        float s = 0.f, comp = 0.f, es = 0.f, ecomp = 0.f;
        for (int k = lane; k < DDIM; k += 32) {
            float a = xr[k], b = er[k];
            float p = __fmul_rn(a, b);
            float pe = __fmaf_rn(a, b, -p);
            float t = __fadd_rn(s, p);
            float z = __fsub_rn(t, s);
            comp = __fadd_rn(comp, __fadd_rn(__fsub_rn(s, __fsub_rn(t, z)), __fsub_rn(p, z)));
            s = t; comp = __fadd_rn(comp, pe);
            float q2 = __fmul_rn(b, b);
            float qe = __fmaf_rn(b, b, -q2);
            float t2 = __fadd_rn(es, q2);
            float z2 = __fsub_rn(t2, es);
            ecomp = __fadd_rn(ecomp, __fadd_rn(__fsub_rn(es, __fsub_rn(t2, z2)), __fsub_rn(q2, z2)));
            es = t2; ecomp = __fadd_rn(ecomp, qe);
        }
        double ds = (double)s + (double)comp;
        double de = (double)es + (double)ecomp;
        #pragma unroll
        for (int o = 16; o; o >>= 1) {
            ds += __shfl_down_sync(0xffffffffu, ds, o);
            de += __shfl_down_sync(0xffffffffu, de, o);
        }
        if (lane == 0) {
            double ne = sqrt(de);
            cval[cI] = ds / ne;
            cinv[cI] = (float)(1.0 / (ne > 1e-12 ? ne : 1e-12));
        }
    }
    __syncthreads();
    __shared__ int wcol_s;
    __shared__ float winv_s;
    if (tid == 0) {
        double best = -1e300; int bc = 0x7fffffff; float bi = 0.f;
        for (int c = 0; c < nc; c++) {
            double v = cval[c]; int col = clist[c];
            if (v > best || (v == best && col < bc)) { best = v; bc = col; bi = cinv[c]; }
        }
        wcol_s = bc; winv_s = bi;
        iout[r] = (float)bc;
    }
    __syncthreads();
    const float* ew = e + (size_t)wcol_s * DDIM;
    const float wi = winv_s;
    qout[(size_t)r * DDIM + tid]       = ew[tid] * wi;
    qout[(size_t)r * DDIM + tid + 256] = ew[tid + 256] * wi;
}

// ---------------- launch ----------------
extern "C" void kernel_launch(void* const* d_in, const int* in_sizes, int n_in,
                              void* d_out, int out_size) {
    (void)in_sizes; (void)n_in; (void)out_size;
    const float* x = (const float*)d_in[0];
    const float* e = (const float*)d_in[1];
    float* qout = (float*)d_out;
    float* iout = qout + (size_t)NROWS * DDIM;
    float* dist = iout + NROWS;

    cudaFuncSetAttribute(k_gemm, cudaFuncAttributeMaxDynamicSharedMemorySize, GEMM_SMEM);
    k_norm<<<NROWS + NCODE, 128>>>(x, e);
    dim3 gg(NCODE / 128, NROWS / 128);
    k_gemm<<<gg, 128, GEMM_SMEM>>>(dist);
    k_refine<<<NROWS, 256>>>(dist, x, e, qout, iout);
}